// round 15
// baseline (speedup 1.0000x reference)
#include <cuda_runtime.h>
#include <math.h>

// Problem constants (fixed shapes for this instance)
#define B_ 8
#define L_ 4096
#define D_ 2048
#define H_ 16
#define HD_ 128
#define NCHUNK 32
#define CHUNK (L_ / NCHUNK)   // 128 keys per chunk
#define NWARP 4
#define IDEPTH 64             // K-slice depth per gemm block (default)

// Scratch (device globals — no allocation allowed)
__device__ float g_qkv[3 * B_ * D_];             // q, k, v after projection (UN-roped)
__device__ float g_trig[2 * 64];                 // cos[0:64], sin[64:128] at pos 4096
__device__ float g_pm[B_ * H_ * NCHUNK];         // partial max
__device__ float g_pl[B_ * H_ * NCHUNK];         // partial sum
__device__ float g_pacc[B_ * H_ * NCHUNK * HD_]; // partial weighted V accum
__device__ float g_attn[B_ * D_];                // attention output before Wo
__device__ float g_sink[1024];                   // warm-kernel sink (never read)

// ---------------------------------------------------------------------------
// prep_main (critical path): zero q region only + build RoPE table.
// ---------------------------------------------------------------------------
__global__ void prep_main() {
    int idx = blockIdx.x * 256 + threadIdx.x;
    if (idx < B_ * D_) g_qkv[idx] = 0.0f;
    if (idx < 64) {
        double inv = pow(10000.0, -(double)idx / 64.0);
        double ang = 4096.0 * inv;
        g_trig[idx]      = (float)cos(ang);
        g_trig[idx + 64] = (float)sin(ang);
    }
}

// ---------------------------------------------------------------------------
// prep_side (side stream): zero k/v regions + d_out.
// ---------------------------------------------------------------------------
__global__ void prep_side(float* __restrict__ out) {
    int idx = blockIdx.x * 256 + threadIdx.x;
    if (idx < 2 * B_ * D_) g_qkv[B_ * D_ + idx] = 0.0f;
    if (idx < B_ * D_) out[idx] = 0.0f;
}

// ---------------------------------------------------------------------------
// Float RoPE using the precomputed table; row = raw 128-dim head vector.
// ---------------------------------------------------------------------------
__device__ __forceinline__ float rope_elem_f(const float* row, int d) {
    int dd = d & 63;
    float c = g_trig[dd], s = g_trig[dd + 64];
    return (d < 64) ? (row[d] * c - row[d + 64] * s)
                    : (row[d - 64] * s + row[d] * c);
}

// ---------------------------------------------------------------------------
// Split-K GEMM (streaming weights), templated K-slice depth.
// Column window selected by caller via W/out base offsets; grid.x = #cols/128.
// grid (jchunks, D_/ID, nz), block 128.
// ---------------------------------------------------------------------------
template<int ID>
__global__ void gemm_kernel(const float* __restrict__ A,
                            const float* __restrict__ W0,
                            const float* __restrict__ W1,
                            float* __restrict__ out) {
    const float* W = (blockIdx.z == 0) ? W0 : W1;
    float* o = out + blockIdx.z * (B_ * D_);

    __shared__ float xs[B_][ID];
    int tid = threadIdx.x;
    int i0 = blockIdx.y * ID;
    for (int t = tid; t < B_ * ID; t += 128) {
        int b = t / ID, i = t % ID;
        xs[b][i] = A[b * D_ + i0 + i];
    }
    __syncthreads();

    int j = blockIdx.x * 128 + tid;
    float acc[B_];
#pragma unroll
    for (int b = 0; b < B_; b++) acc[b] = 0.0f;

    const float* Wp = W + (long)i0 * D_ + j;
#pragma unroll 32
    for (int i = 0; i < ID; i++) {
        float w = __ldcs(&Wp[(long)i * D_]);
#pragma unroll
        for (int b = 0; b < B_; b++) acc[b] += xs[b][i] * w;
    }
#pragma unroll
    for (int b = 0; b < B_; b++) atomicAdd(&o[b * D_ + j], acc[b]);
}

// ---------------------------------------------------------------------------
// Same GEMM, L2-caching weight loads (Wo warmed). K-slice selected by the
// caller via A/W base offsets; grid.y covers the slice depth.
// ---------------------------------------------------------------------------
__global__ void gemm_cached(const float* __restrict__ A,
                            const float* __restrict__ W,
                            float* __restrict__ out) {
    __shared__ float xs[B_][IDEPTH];
    int tid = threadIdx.x;
    int i0 = blockIdx.y * IDEPTH;
    for (int t = tid; t < B_ * IDEPTH; t += 128) {
        int b = t / IDEPTH, i = t % IDEPTH;
        xs[b][i] = A[b * D_ + i0 + i];
    }
    __syncthreads();

    int j = blockIdx.x * 128 + tid;
    float acc[B_];
#pragma unroll
    for (int b = 0; b < B_; b++) acc[b] = 0.0f;

    const float* Wp = W + (long)i0 * D_ + j;
#pragma unroll 16
    for (int i = 0; i < IDEPTH; i++) {
        float w = __ldg(&Wp[(long)i * D_]);
#pragma unroll
        for (int b = 0; b < B_; b++) acc[b] += xs[b][i] * w;
    }
#pragma unroll
    for (int b = 0; b < B_; b++) atomicAdd(&out[b * D_ + j], acc[b]);
}

// ---------------------------------------------------------------------------
// Warm Wo into L2 during the attention scan (side stream).
// ---------------------------------------------------------------------------
__global__ void warm_kernel(const float* __restrict__ W) {
    int idx = blockIdx.x * 256 + threadIdx.x;
    const float4* w4 = (const float4*)W;
    float s = 0.0f;
#pragma unroll
    for (int k = 0; k < 16; k++) {
        float4 v = __ldg(&w4[idx + k * 65536]);
        s += v.x + v.y + v.z + v.w;
    }
    g_sink[idx & 1023] = s;
}

// ---------------------------------------------------------------------------
// Flash-decode partial: one block per (chunk, head, batch). h0 = head offset.
// grid (NCHUNK, 8, B_), block 128 (4 warps) -> 2048 blocks per half.
// ---------------------------------------------------------------------------
__global__ void attn_partial(const float* __restrict__ kc,
                             const float* __restrict__ vc, int h0) {
    int c = blockIdx.x, h = blockIdx.y + h0, b = blockIdx.z;
    int tid = threadIdx.x, w = tid >> 5, lane = tid & 31;

    __shared__ float qraw[HD_];
    __shared__ float qs[HD_];
    __shared__ float sm_m[NWARP], sm_l[NWARP];
    __shared__ float sm_acc[NWARP][HD_];

    const float scale = 0.08838834764831845f;  // 1/sqrt(128)
    qraw[tid] = g_qkv[b * D_ + h * HD_ + tid];
    __syncthreads();
    qs[tid] = rope_elem_f(qraw, tid) * scale;
    __syncthreads();

    float4 qv = *(const float4*)&qs[lane * 4];

    float m = -1e30f, l = 0.0f;
    float4 acc = make_float4(0.f, 0.f, 0.f, 0.f);

    const long RS = (long)H_ * HD_;
    const float* kp = kc + ((long)b * L_ * H_ + h) * HD_
                         + (long)(c * CHUNK + w * 2) * RS + lane * 4;
    const float* vp = vc + ((long)b * L_ * H_ + h) * HD_
                         + (long)(c * CHUNK + w * 2) * RS + lane * 4;

    const int NIT = CHUNK / (NWARP * 2);  // 16

    float4 k0 = __ldcs((const float4*)kp);
    float4 k1 = __ldcs((const float4*)(kp + RS));
    float4 v0 = __ldcs((const float4*)vp);
    float4 v1 = __ldcs((const float4*)(vp + RS));

    for (int it = 0; it < NIT; it++) {
        float4 ck0 = k0, ck1 = k1, cv0 = v0, cv1 = v1;
        if (it + 1 < NIT) {
            long off = (long)(it + 1) * (NWARP * 2) * RS;
            k0 = __ldcs((const float4*)(kp + off));
            k1 = __ldcs((const float4*)(kp + off + RS));
            v0 = __ldcs((const float4*)(vp + off));
            v1 = __ldcs((const float4*)(vp + off + RS));
        }

        float s0 = qv.x * ck0.x + qv.y * ck0.y + qv.z * ck0.z + qv.w * ck0.w;
        float s1 = qv.x * ck1.x + qv.y * ck1.y + qv.z * ck1.z + qv.w * ck1.w;
#pragma unroll
        for (int st = 16; st > 0; st >>= 1) {
            s0 += __shfl_xor_sync(0xFFFFFFFFu, s0, st);
            s1 += __shfl_xor_sync(0xFFFFFFFFu, s1, st);
        }

        float mn = fmaxf(m, fmaxf(s0, s1));
        float f  = __expf(m - mn);
        float p0 = __expf(s0 - mn);
        float p1 = __expf(s1 - mn);
        m = mn;
        l = l * f + p0 + p1;
        acc.x = acc.x * f + p0 * cv0.x + p1 * cv1.x;
        acc.y = acc.y * f + p0 * cv0.y + p1 * cv1.y;
        acc.z = acc.z * f + p0 * cv0.z + p1 * cv1.z;
        acc.w = acc.w * f + p0 * cv0.w + p1 * cv1.w;
    }

    if (lane == 0) { sm_m[w] = m; sm_l[w] = l; }
    *(float4*)&sm_acc[w][lane * 4] = acc;
    __syncthreads();

    if (w == 0) {
        float bm = fmaxf(fmaxf(sm_m[0], sm_m[1]), fmaxf(sm_m[2], sm_m[3]));
        float bl = 0.0f;
        float4 ba = make_float4(0.f, 0.f, 0.f, 0.f);
#pragma unroll
        for (int i = 0; i < NWARP; i++) {
            float f = __expf(sm_m[i] - bm);
            bl += sm_l[i] * f;
            float4 a = *(float4*)&sm_acc[i][lane * 4];
            ba.x += a.x * f; ba.y += a.y * f; ba.z += a.z * f; ba.w += a.w * f;
        }
        int pidx = (b * H_ + h) * NCHUNK + c;
        if (lane == 0) { g_pm[pidx] = bm; g_pl[pidx] = bl; }
        *(float4*)&g_pacc[pidx * HD_ + lane * 4] = ba;
    }
}

// ---------------------------------------------------------------------------
// Combine chunk partials + new-token contribution. h0 = head offset.
// grid (8, B_), block 128 (thread d owns dim d)
// ---------------------------------------------------------------------------
__global__ void attn_combine(int h0) {
    int h = blockIdx.x + h0, b = blockIdx.y, d = threadIdx.x;
    const float scale = 0.08838834764831845f;

    __shared__ float qraw[HD_], kraw[HD_];
    __shared__ float red[HD_];
    qraw[d] = g_qkv[b * D_ + h * HD_ + d];
    kraw[d] = g_qkv[B_ * D_ + b * D_ + h * HD_ + d];
    __syncthreads();

    float qr = rope_elem_f(qraw, d);
    float kr = rope_elem_f(kraw, d);
    red[d] = qr * kr;
    __syncthreads();
    for (int st = 64; st > 0; st >>= 1) {
        if (d < st) red[d] += red[d + st];
        __syncthreads();
    }
    float s_new = red[0] * scale;

    int base = (b * H_ + h) * NCHUNK;
    float M = s_new;
#pragma unroll
    for (int i = 0; i < NCHUNK; i++) M = fmaxf(M, g_pm[base + i]);
    float pn = __expf(s_new - M);
    float L = pn;
    float o = pn * g_qkv[2 * B_ * D_ + b * D_ + h * HD_ + d];  // v_new (no rope)
#pragma unroll
    for (int i = 0; i < NCHUNK; i++) {
        float f = __expf(g_pm[base + i] - M);
        L += g_pl[base + i] * f;
        o += f * g_pacc[(base + i) * HD_ + d];
    }
    g_attn[b * D_ + h * HD_ + d] = o / L;
}

// ---------------------------------------------------------------------------
// Launch: R13 head-split pipeline, NCHUNK=32 scan halves.
//   s0: prep_main -> gemmQ[h0-7](ID=32) -> attn[h0-7] -> attn[h8-15]
//       -> combine[h8-15] -> gemmWo rows 1024-2047
//   s1: prep_side -> gemmQ[h8-15] -> gemmKV -> warm Wo
//       -> combine[h0-7] -> gemmWo rows 0-1023  (joined via ev_w1)
// ---------------------------------------------------------------------------
extern "C" void kernel_launch(void* const* d_in, const int* in_sizes, int n_in,
                              void* d_out, int out_size) {
    const float* x  = (const float*)d_in[0];
    const float* kc = (const float*)d_in[1];
    const float* vc = (const float*)d_in[2];
    const float* Wq = (const float*)d_in[3];
    const float* Wk = (const float*)d_in[4];
    const float* Wv = (const float*)d_in[5];
    const float* Wo = (const float*)d_in[6];
    float* out = (float*)d_out;

    float* g_qkv_p;  cudaGetSymbolAddress((void**)&g_qkv_p, g_qkv);
    float* g_attn_p; cudaGetSymbolAddress((void**)&g_attn_p, g_attn);

    static cudaStream_t s1 = nullptr;
    static cudaEvent_t ev0 = nullptr, ev_q1 = nullptr, ev_q2 = nullptr,
                       ev_kv = nullptr, ev_a1 = nullptr, ev_w1 = nullptr;
    if (!s1) {
        cudaStreamCreateWithFlags(&s1, cudaStreamNonBlocking);
        cudaEventCreateWithFlags(&ev0, cudaEventDisableTiming);
        cudaEventCreateWithFlags(&ev_q1, cudaEventDisableTiming);
        cudaEventCreateWithFlags(&ev_q2, cudaEventDisableTiming);
        cudaEventCreateWithFlags(&ev_kv, cudaEventDisableTiming);
        cudaEventCreateWithFlags(&ev_a1, cudaEventDisableTiming);
        cudaEventCreateWithFlags(&ev_w1, cudaEventDisableTiming);
    }
    cudaStream_t s0 = 0;

    const int HALF = 1024;  // 8 heads * HD_

    // s0: minimal prep (zero q + trig), then q projection heads 0-7 (ID=32)
    prep_main<<<(B_ * D_ + 255) / 256, 256, 0, s0>>>();
    cudaEventRecord(ev0, s0);
    gemm_kernel<32><<<dim3(8, D_ / 32, 1), 128, 0, s0>>>(x, Wq, Wq, g_qkv_p);
    cudaEventRecord(ev_q1, s0);

    // s1: zero k/v/out, then q heads 8-15, kv projections, Wo warm
    cudaStreamWaitEvent(s1, ev0, 0);
    prep_side<<<(2 * B_ * D_ + 255) / 256, 256, 0, s1>>>(out);
    cudaStreamWaitEvent(s1, ev_q1, 0);
    gemm_kernel<64><<<dim3(8, D_ / 64, 1), 128, 0, s1>>>(x, Wq + HALF, Wq + HALF, g_qkv_p + HALF);
    cudaEventRecord(ev_q2, s1);
    gemm_kernel<64><<<dim3(D_ / 128, D_ / 64, 2), 128, 0, s1>>>(x, Wk, Wv, g_qkv_p + B_ * D_);
    cudaEventRecord(ev_kv, s1);
    warm_kernel<<<256, 256, 0, s1>>>(Wo);

    // s0: attention heads 0-7 (2048 blocks)
    attn_partial<<<dim3(NCHUNK, 8, B_), 128, 0, s0>>>(kc, vc, 0);
    cudaEventRecord(ev_a1, s0);

    // s1: combine heads 0-7 + gemmWo rows [0,1024) — under attn_h2
    cudaStreamWaitEvent(s1, ev_a1, 0);
    attn_combine<<<dim3(8, B_), HD_, 0, s1>>>(0);
    gemm_cached<<<dim3(D_ / 128, HALF / IDEPTH, 1), 128, 0, s1>>>(g_attn_p, Wo, out);
    cudaEventRecord(ev_w1, s1);

    // s0: attention heads 8-15 (2048 blocks)
    cudaStreamWaitEvent(s0, ev_q2, 0);
    attn_partial<<<dim3(NCHUNK, 8, B_), 128, 0, s0>>>(kc, vc, 8);

    // s0: combine heads 8-15 (needs k_new/v_new), then gemmWo rows [1024,2048)
    cudaStreamWaitEvent(s0, ev_kv, 0);
    attn_combine<<<dim3(8, B_), HD_, 0, s0>>>(8);
    cudaStreamWaitEvent(s0, ev_w1, 0);  // join s1 leaf
    gemm_cached<<<dim3(D_ / 128, HALF / IDEPTH, 1), 128, 0, s0>>>(
        g_attn_p + HALF, Wo + (long)HALF * D_, out);
}

// round 16
// speedup vs baseline: 1.0423x; 1.0423x over previous
#include <cuda_runtime.h>
#include <math.h>

// Problem constants (fixed shapes for this instance)
#define B_ 8
#define L_ 4096
#define D_ 2048
#define H_ 16
#define HD_ 128
#define NCHUNK 16
#define CHUNK (L_ / NCHUNK)   // 256
#define NWARP 4

// Scratch (device globals — no allocation allowed)
__device__ float g_qkv[3 * B_ * D_];             // q, k, v after projection (UN-roped)
__device__ float g_trig[2 * 64];                 // cos[0:64], sin[64:128] at pos 4096
__device__ float g_pm[B_ * H_ * NCHUNK];         // partial max
__device__ float g_pl[B_ * H_ * NCHUNK];         // partial sum
__device__ float g_pacc[B_ * H_ * NCHUNK * HD_]; // partial weighted V accum
__device__ float g_attn[B_ * D_];                // attention output before Wo
__device__ float g_sink[1024];                   // warm-kernel sink (never read)

// ---------------------------------------------------------------------------
// prep_main (critical path): zero q region only + build RoPE table.
// ---------------------------------------------------------------------------
__global__ void prep_main() {
    int idx = blockIdx.x * 256 + threadIdx.x;
    if (idx < B_ * D_) g_qkv[idx] = 0.0f;
    if (idx < 64) {
        double inv = pow(10000.0, -(double)idx / 64.0);
        double ang = 4096.0 * inv;
        g_trig[idx]      = (float)cos(ang);
        g_trig[idx + 64] = (float)sin(ang);
    }
}

// ---------------------------------------------------------------------------
// prep_side (side stream): zero k/v regions + d_out.
// ---------------------------------------------------------------------------
__global__ void prep_side(float* __restrict__ out) {
    int idx = blockIdx.x * 256 + threadIdx.x;
    if (idx < 2 * B_ * D_) g_qkv[B_ * D_ + idx] = 0.0f;
    if (idx < B_ * D_) out[idx] = 0.0f;
}

// ---------------------------------------------------------------------------
// Float RoPE using the precomputed table; row = raw 128-dim head vector.
// ---------------------------------------------------------------------------
__device__ __forceinline__ float rope_elem_f(const float* row, int d) {
    int dd = d & 63;
    float c = g_trig[dd], s = g_trig[dd + 64];
    return (d < 64) ? (row[d] * c - row[d + 64] * s)
                    : (row[d - 64] * s + row[d] * c);
}

// ---------------------------------------------------------------------------
// Split-K GEMM (streaming weights), templated K-slice depth.
// Column window selected by caller via W/out base offsets; grid.x = #cols/128.
// grid (jchunks, D_/ID, nz), block 128.
// ---------------------------------------------------------------------------
template<int ID>
__global__ void gemm_kernel(const float* __restrict__ A,
                            const float* __restrict__ W0,
                            const float* __restrict__ W1,
                            float* __restrict__ out) {
    const float* W = (blockIdx.z == 0) ? W0 : W1;
    float* o = out + blockIdx.z * (B_ * D_);

    __shared__ float xs[B_][ID];
    int tid = threadIdx.x;
    int i0 = blockIdx.y * ID;
    for (int t = tid; t < B_ * ID; t += 128) {
        int b = t / ID, i = t % ID;
        xs[b][i] = A[b * D_ + i0 + i];
    }
    __syncthreads();

    int j = blockIdx.x * 128 + tid;
    float acc[B_];
#pragma unroll
    for (int b = 0; b < B_; b++) acc[b] = 0.0f;

    const float* Wp = W + (long)i0 * D_ + j;
#pragma unroll 16
    for (int i = 0; i < ID; i++) {
        float w = __ldcs(&Wp[(long)i * D_]);
#pragma unroll
        for (int b = 0; b < B_; b++) acc[b] += xs[b][i] * w;
    }
#pragma unroll
    for (int b = 0; b < B_; b++) atomicAdd(&o[b * D_ + j], acc[b]);
}

// ---------------------------------------------------------------------------
// Same GEMM, L2-caching weight loads (Wo warmed), templated depth.
// K-slice selected by the caller via A/W base offsets.
// ---------------------------------------------------------------------------
template<int ID>
__global__ void gemm_cached(const float* __restrict__ A,
                            const float* __restrict__ W,
                            float* __restrict__ out) {
    __shared__ float xs[B_][ID];
    int tid = threadIdx.x;
    int i0 = blockIdx.y * ID;
    for (int t = tid; t < B_ * ID; t += 128) {
        int b = t / ID, i = t % ID;
        xs[b][i] = A[b * D_ + i0 + i];
    }
    __syncthreads();

    int j = blockIdx.x * 128 + tid;
    float acc[B_];
#pragma unroll
    for (int b = 0; b < B_; b++) acc[b] = 0.0f;

    const float* Wp = W + (long)i0 * D_ + j;
#pragma unroll 16
    for (int i = 0; i < ID; i++) {
        float w = __ldg(&Wp[(long)i * D_]);
#pragma unroll
        for (int b = 0; b < B_; b++) acc[b] += xs[b][i] * w;
    }
#pragma unroll
    for (int b = 0; b < B_; b++) atomicAdd(&out[b * D_ + j], acc[b]);
}

// ---------------------------------------------------------------------------
// Warm Wo into L2 during the attention scan (side stream).
// ---------------------------------------------------------------------------
__global__ void warm_kernel(const float* __restrict__ W) {
    int idx = blockIdx.x * 256 + threadIdx.x;
    const float4* w4 = (const float4*)W;
    float s = 0.0f;
#pragma unroll
    for (int k = 0; k < 16; k++) {
        float4 v = __ldg(&w4[idx + k * 65536]);
        s += v.x + v.y + v.z + v.w;
    }
    g_sink[idx & 1023] = s;
}

// ---------------------------------------------------------------------------
// Flash-decode partial: one block per (chunk, head, batch). h0 = head offset.
// grid (NCHUNK, 8, B_), block 128 (4 warps)
// ---------------------------------------------------------------------------
__global__ void attn_partial(const float* __restrict__ kc,
                             const float* __restrict__ vc, int h0) {
    int c = blockIdx.x, h = blockIdx.y + h0, b = blockIdx.z;
    int tid = threadIdx.x, w = tid >> 5, lane = tid & 31;

    __shared__ float qraw[HD_];
    __shared__ float qs[HD_];
    __shared__ float sm_m[NWARP], sm_l[NWARP];
    __shared__ float sm_acc[NWARP][HD_];

    const float scale = 0.08838834764831845f;  // 1/sqrt(128)
    qraw[tid] = g_qkv[b * D_ + h * HD_ + tid];
    __syncthreads();
    qs[tid] = rope_elem_f(qraw, tid) * scale;
    __syncthreads();

    float4 qv = *(const float4*)&qs[lane * 4];

    float m = -1e30f, l = 0.0f;
    float4 acc = make_float4(0.f, 0.f, 0.f, 0.f);

    const long RS = (long)H_ * HD_;
    const float* kp = kc + ((long)b * L_ * H_ + h) * HD_
                         + (long)(c * CHUNK + w * 2) * RS + lane * 4;
    const float* vp = vc + ((long)b * L_ * H_ + h) * HD_
                         + (long)(c * CHUNK + w * 2) * RS + lane * 4;

    const int NIT = CHUNK / (NWARP * 2);  // 32

    float4 k0 = __ldcs((const float4*)kp);
    float4 k1 = __ldcs((const float4*)(kp + RS));
    float4 v0 = __ldcs((const float4*)vp);
    float4 v1 = __ldcs((const float4*)(vp + RS));

    for (int it = 0; it < NIT; it++) {
        float4 ck0 = k0, ck1 = k1, cv0 = v0, cv1 = v1;
        if (it + 1 < NIT) {
            long off = (long)(it + 1) * (NWARP * 2) * RS;
            k0 = __ldcs((const float4*)(kp + off));
            k1 = __ldcs((const float4*)(kp + off + RS));
            v0 = __ldcs((const float4*)(vp + off));
            v1 = __ldcs((const float4*)(vp + off + RS));
        }

        float s0 = qv.x * ck0.x + qv.y * ck0.y + qv.z * ck0.z + qv.w * ck0.w;
        float s1 = qv.x * ck1.x + qv.y * ck1.y + qv.z * ck1.z + qv.w * ck1.w;
#pragma unroll
        for (int st = 16; st > 0; st >>= 1) {
            s0 += __shfl_xor_sync(0xFFFFFFFFu, s0, st);
            s1 += __shfl_xor_sync(0xFFFFFFFFu, s1, st);
        }

        float mn = fmaxf(m, fmaxf(s0, s1));
        float f  = __expf(m - mn);
        float p0 = __expf(s0 - mn);
        float p1 = __expf(s1 - mn);
        m = mn;
        l = l * f + p0 + p1;
        acc.x = acc.x * f + p0 * cv0.x + p1 * cv1.x;
        acc.y = acc.y * f + p0 * cv0.y + p1 * cv1.y;
        acc.z = acc.z * f + p0 * cv0.z + p1 * cv1.z;
        acc.w = acc.w * f + p0 * cv0.w + p1 * cv1.w;
    }

    if (lane == 0) { sm_m[w] = m; sm_l[w] = l; }
    *(float4*)&sm_acc[w][lane * 4] = acc;
    __syncthreads();

    if (w == 0) {
        float bm = fmaxf(fmaxf(sm_m[0], sm_m[1]), fmaxf(sm_m[2], sm_m[3]));
        float bl = 0.0f;
        float4 ba = make_float4(0.f, 0.f, 0.f, 0.f);
#pragma unroll
        for (int i = 0; i < NWARP; i++) {
            float f = __expf(sm_m[i] - bm);
            bl += sm_l[i] * f;
            float4 a = *(float4*)&sm_acc[i][lane * 4];
            ba.x += a.x * f; ba.y += a.y * f; ba.z += a.z * f; ba.w += a.w * f;
        }
        int pidx = (b * H_ + h) * NCHUNK + c;
        if (lane == 0) { g_pm[pidx] = bm; g_pl[pidx] = bl; }
        *(float4*)&g_pacc[pidx * HD_ + lane * 4] = ba;
    }
}

// ---------------------------------------------------------------------------
// Combine chunk partials + new-token contribution. h0 = head offset.
// grid (8, B_), block 128 (thread d owns dim d)
// ---------------------------------------------------------------------------
__global__ void attn_combine(int h0) {
    int h = blockIdx.x + h0, b = blockIdx.y, d = threadIdx.x;
    const float scale = 0.08838834764831845f;

    __shared__ float qraw[HD_], kraw[HD_];
    __shared__ float red[HD_];
    qraw[d] = g_qkv[b * D_ + h * HD_ + d];
    kraw[d] = g_qkv[B_ * D_ + b * D_ + h * HD_ + d];
    __syncthreads();

    float qr = rope_elem_f(qraw, d);
    float kr = rope_elem_f(kraw, d);
    red[d] = qr * kr;
    __syncthreads();
    for (int st = 64; st > 0; st >>= 1) {
        if (d < st) red[d] += red[d + st];
        __syncthreads();
    }
    float s_new = red[0] * scale;

    float pm[NCHUNK], pl[NCHUNK];
    float M = s_new;
    int base = (b * H_ + h) * NCHUNK;
#pragma unroll
    for (int i = 0; i < NCHUNK; i++) {
        pm[i] = g_pm[base + i];
        pl[i] = g_pl[base + i];
        M = fmaxf(M, pm[i]);
    }
    float pn = __expf(s_new - M);
    float L = pn;
    float o = pn * g_qkv[2 * B_ * D_ + b * D_ + h * HD_ + d];  // v_new (no rope)
#pragma unroll
    for (int i = 0; i < NCHUNK; i++) {
        float f = __expf(pm[i] - M);
        L += pl[i] * f;
        o += f * g_pacc[(base + i) * HD_ + d];
    }
    g_attn[b * D_ + h * HD_ + d] = o / L;
}

// ---------------------------------------------------------------------------
// Launch: R13 head-split pipeline; front gemmQ ID=16, tail gemmWo ID=32.
//   s0: prep_main -> gemmQ[h0-7](ID=16) -> attn[h0-7] -> attn[h8-15]
//       -> combine[h8-15] -> gemmWo rows 1024-2047 (ID=32)
//   s1: prep_side -> gemmQ[h8-15] -> gemmKV -> warm Wo
//       -> combine[h0-7] -> gemmWo rows 0-1023  (joined via ev_w1)
// ---------------------------------------------------------------------------
extern "C" void kernel_launch(void* const* d_in, const int* in_sizes, int n_in,
                              void* d_out, int out_size) {
    const float* x  = (const float*)d_in[0];
    const float* kc = (const float*)d_in[1];
    const float* vc = (const float*)d_in[2];
    const float* Wq = (const float*)d_in[3];
    const float* Wk = (const float*)d_in[4];
    const float* Wv = (const float*)d_in[5];
    const float* Wo = (const float*)d_in[6];
    float* out = (float*)d_out;

    float* g_qkv_p;  cudaGetSymbolAddress((void**)&g_qkv_p, g_qkv);
    float* g_attn_p; cudaGetSymbolAddress((void**)&g_attn_p, g_attn);

    static cudaStream_t s1 = nullptr;
    static cudaEvent_t ev0 = nullptr, ev_q1 = nullptr, ev_q2 = nullptr,
                       ev_kv = nullptr, ev_a1 = nullptr, ev_w1 = nullptr;
    if (!s1) {
        cudaStreamCreateWithFlags(&s1, cudaStreamNonBlocking);
        cudaEventCreateWithFlags(&ev0, cudaEventDisableTiming);
        cudaEventCreateWithFlags(&ev_q1, cudaEventDisableTiming);
        cudaEventCreateWithFlags(&ev_q2, cudaEventDisableTiming);
        cudaEventCreateWithFlags(&ev_kv, cudaEventDisableTiming);
        cudaEventCreateWithFlags(&ev_a1, cudaEventDisableTiming);
        cudaEventCreateWithFlags(&ev_w1, cudaEventDisableTiming);
    }
    cudaStream_t s0 = 0;

    const int HALF = 1024;  // 8 heads * HD_

    // s0: minimal prep (zero q + trig), then q projection heads 0-7 (ID=16)
    prep_main<<<(B_ * D_ + 255) / 256, 256, 0, s0>>>();
    cudaEventRecord(ev0, s0);
    gemm_kernel<16><<<dim3(8, D_ / 16, 1), 128, 0, s0>>>(x, Wq, Wq, g_qkv_p);
    cudaEventRecord(ev_q1, s0);

    // s1: zero k/v/out, then q heads 8-15, kv projections, Wo warm
    cudaStreamWaitEvent(s1, ev0, 0);
    prep_side<<<(2 * B_ * D_ + 255) / 256, 256, 0, s1>>>(out);
    cudaStreamWaitEvent(s1, ev_q1, 0);
    gemm_kernel<64><<<dim3(8, D_ / 64, 1), 128, 0, s1>>>(x, Wq + HALF, Wq + HALF, g_qkv_p + HALF);
    cudaEventRecord(ev_q2, s1);
    gemm_kernel<64><<<dim3(D_ / 128, D_ / 64, 2), 128, 0, s1>>>(x, Wk, Wv, g_qkv_p + B_ * D_);
    cudaEventRecord(ev_kv, s1);
    warm_kernel<<<256, 256, 0, s1>>>(Wo);

    // s0: attention heads 0-7
    attn_partial<<<dim3(NCHUNK, 8, B_), 128, 0, s0>>>(kc, vc, 0);
    cudaEventRecord(ev_a1, s0);

    // s1: combine heads 0-7 + gemmWo rows [0,1024) — under attn_h2
    cudaStreamWaitEvent(s1, ev_a1, 0);
    attn_combine<<<dim3(8, B_), HD_, 0, s1>>>(0);
    gemm_cached<64><<<dim3(D_ / 128, HALF / 64, 1), 128, 0, s1>>>(g_attn_p, Wo, out);
    cudaEventRecord(ev_w1, s1);

    // s0: attention heads 8-15
    cudaStreamWaitEvent(s0, ev_q2, 0);
    attn_partial<<<dim3(NCHUNK, 8, B_), 128, 0, s0>>>(kc, vc, 8);

    // s0: combine heads 8-15 (needs k_new/v_new), then gemmWo rows [1024,2048)
    cudaStreamWaitEvent(s0, ev_kv, 0);
    attn_combine<<<dim3(8, B_), HD_, 0, s0>>>(8);
    cudaStreamWaitEvent(s0, ev_w1, 0);  // join s1 leaf
    gemm_cached<32><<<dim3(D_ / 128, HALF / 32, 1), 128, 0, s0>>>(
        g_attn_p + HALF, Wo + (long)HALF * D_, out);
}

// round 17
// speedup vs baseline: 1.0576x; 1.0147x over previous
#include <cuda_runtime.h>
#include <math.h>

// Problem constants (fixed shapes for this instance)
#define B_ 8
#define L_ 4096
#define D_ 2048
#define H_ 16
#define HD_ 128
#define NCHUNK 16
#define CHUNK (L_ / NCHUNK)   // 256
#define NWARP 4

// Scratch (device globals — no allocation allowed)
__device__ float g_qkv[3 * B_ * D_];             // q, k, v after projection (UN-roped)
__device__ float g_trig[2 * 64];                 // cos[0:64], sin[64:128] at pos 4096
__device__ float g_pm[B_ * H_ * NCHUNK];         // partial max
__device__ float g_pl[B_ * H_ * NCHUNK];         // partial sum
__device__ float g_pacc[B_ * H_ * NCHUNK * HD_]; // partial weighted V accum
__device__ float g_attn[B_ * D_];                // attention output before Wo
__device__ float g_sink[1024];                   // warm-kernel sink (never read)

// ---------------------------------------------------------------------------
// prep_main (critical path): zero q region only + build RoPE table.
// ---------------------------------------------------------------------------
__global__ void prep_main() {
    int idx = blockIdx.x * 256 + threadIdx.x;
    if (idx < B_ * D_) g_qkv[idx] = 0.0f;
    if (idx < 64) {
        double inv = pow(10000.0, -(double)idx / 64.0);
        double ang = 4096.0 * inv;
        g_trig[idx]      = (float)cos(ang);
        g_trig[idx + 64] = (float)sin(ang);
    }
}

// ---------------------------------------------------------------------------
// prep_side (side stream): zero k/v regions + d_out.
// ---------------------------------------------------------------------------
__global__ void prep_side(float* __restrict__ out) {
    int idx = blockIdx.x * 256 + threadIdx.x;
    if (idx < 2 * B_ * D_) g_qkv[B_ * D_ + idx] = 0.0f;
    if (idx < B_ * D_) out[idx] = 0.0f;
}

// ---------------------------------------------------------------------------
// Float RoPE using the precomputed table; row = raw 128-dim head vector.
// ---------------------------------------------------------------------------
__device__ __forceinline__ float rope_elem_f(const float* row, int d) {
    int dd = d & 63;
    float c = g_trig[dd], s = g_trig[dd + 64];
    return (d < 64) ? (row[d] * c - row[d + 64] * s)
                    : (row[d - 64] * s + row[d] * c);
}

// ---------------------------------------------------------------------------
// Split-K GEMM (streaming weights), templated K-slice depth.
// Column window selected by caller via W/out base offsets; grid.x = #cols/128.
// grid (jchunks, D_/ID, nz), block 128.
// ---------------------------------------------------------------------------
template<int ID>
__global__ void gemm_kernel(const float* __restrict__ A,
                            const float* __restrict__ W0,
                            const float* __restrict__ W1,
                            float* __restrict__ out) {
    const float* W = (blockIdx.z == 0) ? W0 : W1;
    float* o = out + blockIdx.z * (B_ * D_);

    __shared__ float xs[B_][ID];
    int tid = threadIdx.x;
    int i0 = blockIdx.y * ID;
    for (int t = tid; t < B_ * ID; t += 128) {
        int b = t / ID, i = t % ID;
        xs[b][i] = A[b * D_ + i0 + i];
    }
    __syncthreads();

    int j = blockIdx.x * 128 + tid;
    float acc[B_];
#pragma unroll
    for (int b = 0; b < B_; b++) acc[b] = 0.0f;

    const float* Wp = W + (long)i0 * D_ + j;
#pragma unroll 16
    for (int i = 0; i < ID; i++) {
        float w = __ldcs(&Wp[(long)i * D_]);
#pragma unroll
        for (int b = 0; b < B_; b++) acc[b] += xs[b][i] * w;
    }
#pragma unroll
    for (int b = 0; b < B_; b++) atomicAdd(&o[b * D_ + j], acc[b]);
}

// ---------------------------------------------------------------------------
// Same GEMM, L2-caching weight loads (Wo warmed), templated depth.
// K-slice selected by the caller via A/W base offsets.
// ---------------------------------------------------------------------------
template<int ID>
__global__ void gemm_cached(const float* __restrict__ A,
                            const float* __restrict__ W,
                            float* __restrict__ out) {
    __shared__ float xs[B_][ID];
    int tid = threadIdx.x;
    int i0 = blockIdx.y * ID;
    for (int t = tid; t < B_ * ID; t += 128) {
        int b = t / ID, i = t % ID;
        xs[b][i] = A[b * D_ + i0 + i];
    }
    __syncthreads();

    int j = blockIdx.x * 128 + tid;
    float acc[B_];
#pragma unroll
    for (int b = 0; b < B_; b++) acc[b] = 0.0f;

    const float* Wp = W + (long)i0 * D_ + j;
#pragma unroll 16
    for (int i = 0; i < ID; i++) {
        float w = __ldg(&Wp[(long)i * D_]);
#pragma unroll
        for (int b = 0; b < B_; b++) acc[b] += xs[b][i] * w;
    }
#pragma unroll
    for (int b = 0; b < B_; b++) atomicAdd(&out[b * D_ + j], acc[b]);
}

// ---------------------------------------------------------------------------
// Warm Wo into L2 during the attention scan (side stream).
// ---------------------------------------------------------------------------
__global__ void warm_kernel(const float* __restrict__ W) {
    int idx = blockIdx.x * 256 + threadIdx.x;
    const float4* w4 = (const float4*)W;
    float s = 0.0f;
#pragma unroll
    for (int k = 0; k < 16; k++) {
        float4 v = __ldg(&w4[idx + k * 65536]);
        s += v.x + v.y + v.z + v.w;
    }
    g_sink[idx & 1023] = s;
}

// ---------------------------------------------------------------------------
// Flash-decode partial: one block per (chunk, head, batch). h0 = head offset.
// grid (NCHUNK, 8, B_), block 128 (4 warps)
// ---------------------------------------------------------------------------
__global__ void attn_partial(const float* __restrict__ kc,
                             const float* __restrict__ vc, int h0) {
    int c = blockIdx.x, h = blockIdx.y + h0, b = blockIdx.z;
    int tid = threadIdx.x, w = tid >> 5, lane = tid & 31;

    __shared__ float qraw[HD_];
    __shared__ float qs[HD_];
    __shared__ float sm_m[NWARP], sm_l[NWARP];
    __shared__ float sm_acc[NWARP][HD_];

    const float scale = 0.08838834764831845f;  // 1/sqrt(128)
    qraw[tid] = g_qkv[b * D_ + h * HD_ + tid];
    __syncthreads();
    qs[tid] = rope_elem_f(qraw, tid) * scale;
    __syncthreads();

    float4 qv = *(const float4*)&qs[lane * 4];

    float m = -1e30f, l = 0.0f;
    float4 acc = make_float4(0.f, 0.f, 0.f, 0.f);

    const long RS = (long)H_ * HD_;
    const float* kp = kc + ((long)b * L_ * H_ + h) * HD_
                         + (long)(c * CHUNK + w * 2) * RS + lane * 4;
    const float* vp = vc + ((long)b * L_ * H_ + h) * HD_
                         + (long)(c * CHUNK + w * 2) * RS + lane * 4;

    const int NIT = CHUNK / (NWARP * 2);  // 32

    float4 k0 = __ldcs((const float4*)kp);
    float4 k1 = __ldcs((const float4*)(kp + RS));
    float4 v0 = __ldcs((const float4*)vp);
    float4 v1 = __ldcs((const float4*)(vp + RS));

    for (int it = 0; it < NIT; it++) {
        float4 ck0 = k0, ck1 = k1, cv0 = v0, cv1 = v1;
        if (it + 1 < NIT) {
            long off = (long)(it + 1) * (NWARP * 2) * RS;
            k0 = __ldcs((const float4*)(kp + off));
            k1 = __ldcs((const float4*)(kp + off + RS));
            v0 = __ldcs((const float4*)(vp + off));
            v1 = __ldcs((const float4*)(vp + off + RS));
        }

        float s0 = qv.x * ck0.x + qv.y * ck0.y + qv.z * ck0.z + qv.w * ck0.w;
        float s1 = qv.x * ck1.x + qv.y * ck1.y + qv.z * ck1.z + qv.w * ck1.w;
#pragma unroll
        for (int st = 16; st > 0; st >>= 1) {
            s0 += __shfl_xor_sync(0xFFFFFFFFu, s0, st);
            s1 += __shfl_xor_sync(0xFFFFFFFFu, s1, st);
        }

        float mn = fmaxf(m, fmaxf(s0, s1));
        float f  = __expf(m - mn);
        float p0 = __expf(s0 - mn);
        float p1 = __expf(s1 - mn);
        m = mn;
        l = l * f + p0 + p1;
        acc.x = acc.x * f + p0 * cv0.x + p1 * cv1.x;
        acc.y = acc.y * f + p0 * cv0.y + p1 * cv1.y;
        acc.z = acc.z * f + p0 * cv0.z + p1 * cv1.z;
        acc.w = acc.w * f + p0 * cv0.w + p1 * cv1.w;
    }

    if (lane == 0) { sm_m[w] = m; sm_l[w] = l; }
    *(float4*)&sm_acc[w][lane * 4] = acc;
    __syncthreads();

    if (w == 0) {
        float bm = fmaxf(fmaxf(sm_m[0], sm_m[1]), fmaxf(sm_m[2], sm_m[3]));
        float bl = 0.0f;
        float4 ba = make_float4(0.f, 0.f, 0.f, 0.f);
#pragma unroll
        for (int i = 0; i < NWARP; i++) {
            float f = __expf(sm_m[i] - bm);
            bl += sm_l[i] * f;
            float4 a = *(float4*)&sm_acc[i][lane * 4];
            ba.x += a.x * f; ba.y += a.y * f; ba.z += a.z * f; ba.w += a.w * f;
        }
        int pidx = (b * H_ + h) * NCHUNK + c;
        if (lane == 0) { g_pm[pidx] = bm; g_pl[pidx] = bl; }
        *(float4*)&g_pacc[pidx * HD_ + lane * 4] = ba;
    }
}

// ---------------------------------------------------------------------------
// Combine chunk partials + new-token contribution. h0 = head offset.
// grid (8, B_), block 128 (thread d owns dim d)
// ---------------------------------------------------------------------------
__global__ void attn_combine(int h0) {
    int h = blockIdx.x + h0, b = blockIdx.y, d = threadIdx.x;
    const float scale = 0.08838834764831845f;

    __shared__ float qraw[HD_], kraw[HD_];
    __shared__ float red[HD_];
    qraw[d] = g_qkv[b * D_ + h * HD_ + d];
    kraw[d] = g_qkv[B_ * D_ + b * D_ + h * HD_ + d];
    __syncthreads();

    float qr = rope_elem_f(qraw, d);
    float kr = rope_elem_f(kraw, d);
    red[d] = qr * kr;
    __syncthreads();
    for (int st = 64; st > 0; st >>= 1) {
        if (d < st) red[d] += red[d + st];
        __syncthreads();
    }
    float s_new = red[0] * scale;

    float pm[NCHUNK], pl[NCHUNK];
    float M = s_new;
    int base = (b * H_ + h) * NCHUNK;
#pragma unroll
    for (int i = 0; i < NCHUNK; i++) {
        pm[i] = g_pm[base + i];
        pl[i] = g_pl[base + i];
        M = fmaxf(M, pm[i]);
    }
    float pn = __expf(s_new - M);
    float L = pn;
    float o = pn * g_qkv[2 * B_ * D_ + b * D_ + h * HD_ + d];  // v_new (no rope)
#pragma unroll
    for (int i = 0; i < NCHUNK; i++) {
        float f = __expf(pm[i] - M);
        L += pl[i] * f;
        o += f * g_pacc[(base + i) * HD_ + d];
    }
    g_attn[b * D_ + h * HD_ + d] = o / L;
}

// ---------------------------------------------------------------------------
// Launch: R16 head-split pipeline; front gemmQ ID=8, tail gemmWo ID=16.
//   s0: prep_main -> gemmQ[h0-7](ID=8) -> attn[h0-7] -> attn[h8-15]
//       -> combine[h8-15] -> gemmWo rows 1024-2047 (ID=16)
//   s1: prep_side -> gemmQ[h8-15] -> gemmKV -> warm Wo
//       -> combine[h0-7] -> gemmWo rows 0-1023  (joined via ev_w1)
// ---------------------------------------------------------------------------
extern "C" void kernel_launch(void* const* d_in, const int* in_sizes, int n_in,
                              void* d_out, int out_size) {
    const float* x  = (const float*)d_in[0];
    const float* kc = (const float*)d_in[1];
    const float* vc = (const float*)d_in[2];
    const float* Wq = (const float*)d_in[3];
    const float* Wk = (const float*)d_in[4];
    const float* Wv = (const float*)d_in[5];
    const float* Wo = (const float*)d_in[6];
    float* out = (float*)d_out;

    float* g_qkv_p;  cudaGetSymbolAddress((void**)&g_qkv_p, g_qkv);
    float* g_attn_p; cudaGetSymbolAddress((void**)&g_attn_p, g_attn);

    static cudaStream_t s1 = nullptr;
    static cudaEvent_t ev0 = nullptr, ev_q1 = nullptr, ev_q2 = nullptr,
                       ev_kv = nullptr, ev_a1 = nullptr, ev_w1 = nullptr;
    if (!s1) {
        cudaStreamCreateWithFlags(&s1, cudaStreamNonBlocking);
        cudaEventCreateWithFlags(&ev0, cudaEventDisableTiming);
        cudaEventCreateWithFlags(&ev_q1, cudaEventDisableTiming);
        cudaEventCreateWithFlags(&ev_q2, cudaEventDisableTiming);
        cudaEventCreateWithFlags(&ev_kv, cudaEventDisableTiming);
        cudaEventCreateWithFlags(&ev_a1, cudaEventDisableTiming);
        cudaEventCreateWithFlags(&ev_w1, cudaEventDisableTiming);
    }
    cudaStream_t s0 = 0;

    const int HALF = 1024;  // 8 heads * HD_

    // s0: minimal prep (zero q + trig), then q projection heads 0-7 (ID=8)
    prep_main<<<(B_ * D_ + 255) / 256, 256, 0, s0>>>();
    cudaEventRecord(ev0, s0);
    gemm_kernel<8><<<dim3(8, D_ / 8, 1), 128, 0, s0>>>(x, Wq, Wq, g_qkv_p);
    cudaEventRecord(ev_q1, s0);

    // s1: zero k/v/out, then q heads 8-15, kv projections, Wo warm
    cudaStreamWaitEvent(s1, ev0, 0);
    prep_side<<<(2 * B_ * D_ + 255) / 256, 256, 0, s1>>>(out);
    cudaStreamWaitEvent(s1, ev_q1, 0);
    gemm_kernel<64><<<dim3(8, D_ / 64, 1), 128, 0, s1>>>(x, Wq + HALF, Wq + HALF, g_qkv_p + HALF);
    cudaEventRecord(ev_q2, s1);
    gemm_kernel<64><<<dim3(D_ / 128, D_ / 64, 2), 128, 0, s1>>>(x, Wk, Wv, g_qkv_p + B_ * D_);
    cudaEventRecord(ev_kv, s1);
    warm_kernel<<<256, 256, 0, s1>>>(Wo);

    // s0: attention heads 0-7
    attn_partial<<<dim3(NCHUNK, 8, B_), 128, 0, s0>>>(kc, vc, 0);
    cudaEventRecord(ev_a1, s0);

    // s1: combine heads 0-7 + gemmWo rows [0,1024) — under attn_h2
    cudaStreamWaitEvent(s1, ev_a1, 0);
    attn_combine<<<dim3(8, B_), HD_, 0, s1>>>(0);
    gemm_cached<64><<<dim3(D_ / 128, HALF / 64, 1), 128, 0, s1>>>(g_attn_p, Wo, out);
    cudaEventRecord(ev_w1, s1);

    // s0: attention heads 8-15
    cudaStreamWaitEvent(s0, ev_q2, 0);
    attn_partial<<<dim3(NCHUNK, 8, B_), 128, 0, s0>>>(kc, vc, 8);

    // s0: combine heads 8-15 (needs k_new/v_new), then gemmWo rows [1024,2048)
    cudaStreamWaitEvent(s0, ev_kv, 0);
    attn_combine<<<dim3(8, B_), HD_, 0, s0>>>(8);
    cudaStreamWaitEvent(s0, ev_w1, 0);  // join s1 leaf
    gemm_cached<16><<<dim3(D_ / 128, HALF / 16, 1), 128, 0, s0>>>(
        g_attn_p + HALF, Wo + (long)HALF * D_, out);
}